// round 13
// baseline (speedup 1.0000x reference)
#include <cuda_runtime.h>
#include <cuda_bf16.h>
#include <mma.h>
#include <math.h>

using namespace nvcuda;

#define B_  2
#define S_  2048
#define D_  1024
#define H_  16
#define HD_ 64
#define KSEL 409
#define RANK0 (S_ - KSEL)   /* 1639 */
#define MROWS (B_ * S_)     /* 4096 */

// ---------------- device scratch ----------------
__device__ __align__(256) float g_Q[MROWS * D_];                 // [b,h,s,hd] fp32
__device__ __align__(256) __nv_bfloat16 g_K3[3][MROWS * D_];     // K planes [b,h,s,hd]
__device__ __align__(256) __nv_bfloat16 g_V2[2][MROWS * D_];     // V planes
__device__ __align__(256) __nv_bfloat16 g_X3[3][MROWS * D_];     // X planes
__device__ __align__(256) __nv_bfloat16 g_A3[2][MROWS * D_];     // attn-out planes [b,s,d]
__device__ __align__(256) __nv_bfloat16 g_W3[3][D_ * D_];        // weight planes

// ---------------- split3 ----------------
__global__ __launch_bounds__(256) void split3_kernel(
    const float* __restrict__ src,
    __nv_bfloat16* __restrict__ d0, __nv_bfloat16* __restrict__ d1,
    __nv_bfloat16* __restrict__ d2, int n4)
{
    int i = blockIdx.x * 256 + threadIdx.x;
    if (i >= n4) return;
    float4 v = ((const float4*)src)[i];
    float va[4] = { v.x, v.y, v.z, v.w };
    unsigned short u0[4], u1[4], u2[4];
#pragma unroll
    for (int e = 0; e < 4; e++) {
        float r = va[e];
        __nv_bfloat16 b0 = __float2bfloat16(r);  r -= __bfloat162float(b0);
        __nv_bfloat16 b1 = __float2bfloat16(r);  r -= __bfloat162float(b1);
        __nv_bfloat16 b2 = __float2bfloat16(r);
        u0[e] = __bfloat16_as_ushort(b0);
        u1[e] = __bfloat16_as_ushort(b1);
        u2[e] = __bfloat16_as_ushort(b2);
    }
    uint2 w;
    w.x = (unsigned)u0[0] | ((unsigned)u0[1] << 16);
    w.y = (unsigned)u0[2] | ((unsigned)u0[3] << 16);
    ((uint2*)d0)[i] = w;
    w.x = (unsigned)u1[0] | ((unsigned)u1[1] << 16);
    w.y = (unsigned)u1[2] | ((unsigned)u1[3] << 16);
    ((uint2*)d1)[i] = w;
    if (d2) {
        w.x = (unsigned)u2[0] | ((unsigned)u2[1] << 16);
        w.y = (unsigned)u2[2] | ((unsigned)u2[3] << 16);
        ((uint2*)d2)[i] = w;
    }
}

// ======== pipelined split-bf16 GEMM with fused split epilogue ========
#define GBKP 40
#define GSTG 36
#define PLANE_SZ (128 * GBKP)
#define GEMM_SMEM_3 (2 * 3 * 2 * PLANE_SZ * 2)
#define GEMM_SMEM_2 (2 * 2 * 2 * PLANE_SZ * 2)

template<int PLANES>
__global__ __launch_bounds__(256, 1) void gemm_pipe(
    const __nv_bfloat16* __restrict__ A0, const __nv_bfloat16* __restrict__ A1,
    const __nv_bfloat16* __restrict__ A2,
    const __nv_bfloat16* __restrict__ B0, const __nv_bfloat16* __restrict__ B1,
    const __nv_bfloat16* __restrict__ B2,
    const float* __restrict__ bias, float* __restrict__ C,
    __nv_bfloat16* __restrict__ P0, __nv_bfloat16* __restrict__ P1,
    __nv_bfloat16* __restrict__ P2, int mode)
{
    extern __shared__ char smraw[];
    __nv_bfloat16* sbase = (__nv_bfloat16*)smraw;
    const int STAGE_SZ = PLANES * 2 * PLANE_SZ;
    const __nv_bfloat16* Ap[3] = { A0, A1, A2 };
    const __nv_bfloat16* Bp[3] = { B0, B1, B2 };

    const int K = D_;
    int tid = threadIdx.x;
    int wid = tid >> 5;
    int wm = wid >> 2;
    int wn = wid & 3;
    int bm = blockIdx.y * 128;
    int bn = blockIdx.x * 128;

    wmma::fragment<wmma::accumulator, 16, 16, 16, float> fc[4][2];
#pragma unroll
    for (int i = 0; i < 4; i++)
#pragma unroll
        for (int j = 0; j < 2; j++) wmma::fill_fragment(fc[i][j], 0.0f);

    int row0 = tid >> 2, col0 = (tid & 3) * 8;
    int row1 = (tid + 256) >> 2, col1 = ((tid + 256) & 3) * 8;

    auto load_stage = [&](int t, int buf) {
        int k0 = t * 32;
#pragma unroll
        for (int p = 0; p < PLANES; p++) {
            __nv_bfloat16* sA = sbase + buf * STAGE_SZ + p * PLANE_SZ;
            __nv_bfloat16* sB = sbase + buf * STAGE_SZ + (PLANES + p) * PLANE_SZ;
            {
                const __nv_bfloat16* ga = Ap[p] + (size_t)(bm + row0) * K + k0 + col0;
                const __nv_bfloat16* gb = Bp[p] + (size_t)(bn + row0) * K + k0 + col0;
                unsigned da = (unsigned)__cvta_generic_to_shared(sA + row0 * GBKP + col0);
                unsigned db = (unsigned)__cvta_generic_to_shared(sB + row0 * GBKP + col0);
                asm volatile("cp.async.cg.shared.global [%0], [%1], 16;" :: "r"(da), "l"(ga));
                asm volatile("cp.async.cg.shared.global [%0], [%1], 16;" :: "r"(db), "l"(gb));
            }
            {
                const __nv_bfloat16* ga = Ap[p] + (size_t)(bm + row1) * K + k0 + col1;
                const __nv_bfloat16* gb = Bp[p] + (size_t)(bn + row1) * K + k0 + col1;
                unsigned da = (unsigned)__cvta_generic_to_shared(sA + row1 * GBKP + col1);
                unsigned db = (unsigned)__cvta_generic_to_shared(sB + row1 * GBKP + col1);
                asm volatile("cp.async.cg.shared.global [%0], [%1], 16;" :: "r"(da), "l"(ga));
                asm volatile("cp.async.cg.shared.global [%0], [%1], 16;" :: "r"(db), "l"(gb));
            }
        }
        asm volatile("cp.async.commit_group;");
    };

    load_stage(0, 0);
    load_stage(1, 1);

    const int NT = K / 32;
    for (int t = 0; t < NT; t++) {
        if (t + 1 < NT) asm volatile("cp.async.wait_group 1;");
        else            asm volatile("cp.async.wait_group 0;");
        __syncthreads();

        int buf = t & 1;
        __nv_bfloat16* stA = sbase + buf * STAGE_SZ;
        __nv_bfloat16* stB = stA + PLANES * PLANE_SZ;
#pragma unroll
        for (int ks = 0; ks < 2; ks++) {
            wmma::fragment<wmma::matrix_b, 16, 16, 16, __nv_bfloat16, wmma::col_major> fb[PLANES][2];
#pragma unroll
            for (int p = 0; p < PLANES; p++)
#pragma unroll
                for (int j = 0; j < 2; j++)
                    wmma::load_matrix_sync(fb[p][j],
                        stB + p * PLANE_SZ + (wn * 32 + j * 16) * GBKP + ks * 16, GBKP);
#pragma unroll
            for (int sa = 0; sa < PLANES; sa++) {
                wmma::fragment<wmma::matrix_a, 16, 16, 16, __nv_bfloat16, wmma::row_major> fa[4];
#pragma unroll
                for (int i = 0; i < 4; i++)
                    wmma::load_matrix_sync(fa[i],
                        stA + sa * PLANE_SZ + (wm * 64 + i * 16) * GBKP + ks * 16, GBKP);
#pragma unroll
                for (int sb = 0; sb < PLANES - sa; sb++)
#pragma unroll
                    for (int i = 0; i < 4; i++)
#pragma unroll
                        for (int j = 0; j < 2; j++)
                            wmma::mma_sync(fc[i][j], fa[i], fb[sb][j], fc[i][j]);
            }
        }
        __syncthreads();
        if (t + 2 < NT) load_stage(t + 2, buf);
    }

    float* stage = (float*)smraw + wid * 64 * GSTG;
#pragma unroll
    for (int i = 0; i < 4; i++)
#pragma unroll
        for (int j = 0; j < 2; j++)
            wmma::store_matrix_sync(stage + (i * 16) * GSTG + j * 16, fc[i][j],
                                    GSTG, wmma::mem_row_major);
    __syncwarp();

    int lane = tid & 31;
    for (int idx = lane; idx < 64 * 32; idx += 32) {
        int r = idx >> 5, c = idx & 31;
        int gr = bm + wm * 64 + r;
        int gc = bn + wn * 32 + c;
        float v = stage[r * GSTG + c] + bias[gc];
        if (mode == 0) {
            C[(size_t)gr * D_ + gc] = v;
        } else {
            int b = gr >> 11;
            int s = gr & (S_ - 1);
            int h = gc >> 6;
            int hd = gc & (HD_ - 1);
            size_t oi = (((size_t)(b * H_ + h)) * S_ + s) * HD_ + hd;
            if (mode == 1) {
                C[oi] = v;
            } else {
                __nv_bfloat16 b0 = __float2bfloat16(v);
                float r1 = v - __bfloat162float(b0);
                __nv_bfloat16 b1 = __float2bfloat16(r1);
                P0[oi] = b0;
                P1[oi] = b1;
                if (mode == 2) P2[oi] = __float2bfloat16(r1 - __bfloat162float(b1));
            }
        }
    }
}

// ======== tensor-core fused sparse attention ========
#define SCP    2056
#define CH64   64
#define NCH64  (S_ / CH64)          /* 32 */
#define KTP    72

#define KBUF   (3 * CH64 * KTP)
#define VBUF   (2 * CH64 * KTP)
#define PBUF   (2 * 16 * KTP)

#define AT_SC   0
#define AT_KV   131584
#define AT_Q    (AT_KV + 55296)
#define AT_P    (AT_Q + 6912)
#define AT_STG  (AT_P + 9216)
#define AT_RCP  (AT_STG + 16384)
#define AT_SMEM (AT_RCP + 64)

__global__ __launch_bounds__(512, 1) void attn_tc(
    const float* __restrict__ Q,
    const __nv_bfloat16* __restrict__ K0, const __nv_bfloat16* __restrict__ K1,
    const __nv_bfloat16* __restrict__ K2,
    const __nv_bfloat16* __restrict__ V0, const __nv_bfloat16* __restrict__ V1,
    __nv_bfloat16* __restrict__ A0, __nv_bfloat16* __restrict__ A1)
{
    extern __shared__ char smem[];
    float* sc = (float*)(smem + AT_SC);
    __nv_bfloat16* kb = (__nv_bfloat16*)(smem + AT_KV);
    __nv_bfloat16* qt = (__nv_bfloat16*)(smem + AT_Q);
    __nv_bfloat16* pt = (__nv_bfloat16*)(smem + AT_P);
    float* stg   = (float*)(smem + AT_STG);
    int*   hist  = (int*)(smem + AT_STG);
    float* s_rcp = (float*)(smem + AT_RCP);

    int tid  = threadIdx.x;
    int lane = tid & 31;
    int w    = tid >> 5;
    int b    = blockIdx.z, h = blockIdx.y;
    int q0   = blockIdx.x * 16;
    size_t hb = ((size_t)(b * H_ + h)) * S_ * HD_;
    const __nv_bfloat16* Kp[3] = { K0 + hb, K1 + hb, K2 + hb };
    const __nv_bfloat16* Vp[2] = { V0 + hb, V1 + hb };

    auto load_k = [&](int ch) {
#pragma unroll
        for (int it = 0; it < 3; it++) {
            int i = tid + it * 512;
            int plane = i >> 9;
            int rem = i & 511;
            int row = rem >> 3, seg = rem & 7;
            const __nv_bfloat16* g = Kp[plane] + (size_t)(ch * CH64 + row) * HD_ + seg * 8;
            unsigned d = (unsigned)__cvta_generic_to_shared(
                kb + (ch & 1) * KBUF + plane * CH64 * KTP + row * KTP + seg * 8);
            asm volatile("cp.async.cg.shared.global [%0], [%1], 16;" :: "r"(d), "l"(g));
        }
        asm volatile("cp.async.commit_group;");
    };
    auto load_v = [&](int ch) {
#pragma unroll
        for (int it = 0; it < 2; it++) {
            int i = tid + it * 512;
            int plane = i >> 9;
            int rem = i & 511;
            int row = rem >> 3, seg = rem & 7;
            const __nv_bfloat16* g = Vp[plane] + (size_t)(ch * CH64 + row) * HD_ + seg * 8;
            unsigned d = (unsigned)__cvta_generic_to_shared(
                kb + (ch & 1) * VBUF + plane * CH64 * KTP + row * KTP + seg * 8);
            asm volatile("cp.async.cg.shared.global [%0], [%1], 16;" :: "r"(d), "l"(g));
        }
        asm volatile("cp.async.commit_group;");
    };

    load_k(0);
    load_k(1);

    // ---- phase A: Q load, scale 1/8 (exact), 3-split ----
    for (int i = tid; i < 16 * HD_; i += 512) {
        int r = i >> 6, d = i & 63;
        float v = Q[hb + (size_t)(q0 + r) * HD_ + d] * 0.125f;
        __nv_bfloat16 b0 = __float2bfloat16(v);  v -= __bfloat162float(b0);
        __nv_bfloat16 b1 = __float2bfloat16(v);  v -= __bfloat162float(b1);
        __nv_bfloat16 b2 = __float2bfloat16(v);
        qt[0 * 16 * KTP + r * KTP + d] = b0;
        qt[1 * 16 * KTP + r * KTP + d] = b1;
        qt[2 * 16 * KTP + r * KTP + d] = b2;
    }
    __syncthreads();

    int nt = w & 3, kh = w >> 2;
    wmma::fragment<wmma::matrix_a, 16, 16, 16, __nv_bfloat16, wmma::row_major> fqa[3];
#pragma unroll
    for (int p = 0; p < 3; p++)
        wmma::load_matrix_sync(fqa[p], qt + p * 16 * KTP + kh * 16, KTP);

    // ---- phase B: QK^T, 64-key chunks, double-buffered ----
    const int SA[6] = {0, 0, 1, 1, 0, 2};
    const int SB[6] = {0, 1, 0, 1, 2, 0};
    for (int ch = 0; ch < NCH64; ch++) {
        if (ch + 1 < NCH64) asm volatile("cp.async.wait_group 1;");
        else                asm volatile("cp.async.wait_group 0;");
        __syncthreads();

        __nv_bfloat16* kbuf = kb + (ch & 1) * KBUF;
        wmma::fragment<wmma::accumulator, 16, 16, 16, float> acc;
        wmma::fill_fragment(acc, 0.0f);
        {
            wmma::fragment<wmma::matrix_b, 16, 16, 16, __nv_bfloat16, wmma::col_major> fkb[3];
#pragma unroll
            for (int p = 0; p < 3; p++)
                wmma::load_matrix_sync(fkb[p],
                    kbuf + p * CH64 * KTP + (nt * 16) * KTP + kh * 16, KTP);
#pragma unroll
            for (int pr = 0; pr < 6; pr++)
                wmma::mma_sync(acc, fqa[SA[pr]], fkb[SB[pr]], acc);
        }
        if (kh > 0)
            wmma::store_matrix_sync(stg + (nt * 3 + kh - 1) * 256, acc, 16,
                                    wmma::mem_row_major);
        __syncthreads();
        if (kh == 0) {
            wmma::fragment<wmma::accumulator, 16, 16, 16, float> o;
#pragma unroll
            for (int s = 0; s < 3; s++) {
                wmma::load_matrix_sync(o, stg + (nt * 3 + s) * 256, 16,
                                       wmma::mem_row_major);
#pragma unroll
                for (int e = 0; e < acc.num_elements; e++) acc.x[e] += o.x[e];
            }
            wmma::store_matrix_sync(sc + ch * CH64 + nt * 16, acc, SCP,
                                    wmma::mem_row_major);
        }
        if (ch + 2 < NCH64) load_k(ch + 2);
    }
    __syncthreads();

    // V chunk 0/1 loads hidden behind phase C (kb is free)
    load_v(0);
    load_v(1);

    // ---- phase C: radix select (row w) — ballot pass 0, then light atomic passes ----
    {
        const unsigned FULL = 0xffffffffu;
        unsigned pref = 0u; int rank = RANK0;
        const float* rowp = sc + w * SCP;

        // pass 0: 5-bit digit (bits 31..27), 32 bins = 1 per lane, NO atomics
        {
            int cnt = 0;
            for (int i = lane; i < S_; i += 32) {
                unsigned bits = __float_as_uint(rowp[i]);
                unsigned u = (bits & 0x80000000u) ? ~bits : (bits | 0x80000000u);
                unsigned d = u >> 27;
                unsigned b0 = __ballot_sync(FULL, d & 1u);
                unsigned b1 = __ballot_sync(FULL, d & 2u);
                unsigned b2 = __ballot_sync(FULL, d & 4u);
                unsigned b3 = __ballot_sync(FULL, d & 8u);
                unsigned b4 = __ballot_sync(FULL, d & 16u);
                unsigned m = (lane & 1)  ? b0 : ~b0;
                m &= (lane & 2)  ? b1 : ~b1;
                m &= (lane & 4)  ? b2 : ~b2;
                m &= (lane & 8)  ? b3 : ~b3;
                m &= (lane & 16) ? b4 : ~b4;
                cnt += __popc(m);
            }
            int inc = cnt;
#pragma unroll
            for (int off = 1; off < 32; off <<= 1) {
                int n = __shfl_up_sync(FULL, inc, off);
                if (lane >= off) inc += n;
            }
            int excl = inc - cnt;
            bool found = (rank >= excl) && (rank < inc);
            int nrank = rank - excl;
            unsigned mk = __ballot_sync(FULL, found);
            int src = __ffs(mk) - 1;
            rank = __shfl_sync(FULL, nrank, src);
            pref = (unsigned)src << 27;
        }

        // passes 1..4 on remaining 27 bits: (shift,width) = (19,8)(11,8)(3,8)(0,3)
        int* hw = hist + w * 256;
        const int PSH[4] = {19, 11, 3, 0};
        const int PWD[4] = {8, 8, 8, 3};
        for (int pass = 0; pass < 4; pass++) {
            int shift = PSH[pass], width = PWD[pass];
            int okshift = shift + width;
            unsigned dmask = (1u << width) - 1u;
#pragma unroll
            for (int j = lane; j < 256; j += 32) hw[j] = 0;
            __syncwarp();
            for (int i = lane; i < S_; i += 32) {
                unsigned bits = __float_as_uint(rowp[i]);
                unsigned u = (bits & 0x80000000u) ? ~bits : (bits | 0x80000000u);
                if ((u >> okshift) == (pref >> okshift))
                    atomicAdd(&hw[(u >> shift) & dmask], 1);
            }
            __syncwarp();
            int c8[8]; int cnt = 0;
#pragma unroll
            for (int j = 0; j < 8; j++) { c8[j] = hw[lane * 8 + j]; cnt += c8[j]; }
            int inc = cnt;
#pragma unroll
            for (int off = 1; off < 32; off <<= 1) {
                int n = __shfl_up_sync(FULL, inc, off);
                if (lane >= off) inc += n;
            }
            int excl = inc - cnt;
            bool found = (rank >= excl) && (rank < inc);
            unsigned npref = pref; int nrank = rank;
            if (found) {
                int rr = rank - excl; int sel = -1;
#pragma unroll
                for (int j = 0; j < 8; j++) {
                    if (sel < 0) { if (rr < c8[j]) sel = j; else rr -= c8[j]; }
                }
                npref = pref | ((unsigned)(lane * 8 + sel) << shift);
                nrank = rr;
            }
            unsigned mk = __ballot_sync(FULL, found);
            int src = __ffs(mk) - 1;
            pref = __shfl_sync(FULL, npref, src);
            rank = __shfl_sync(FULL, nrank, src);
            __syncwarp();
        }
        unsigned tb = (pref & 0x80000000u) ? (pref ^ 0x80000000u) : ~pref;
        float thr = __uint_as_float(tb);

        // softmax (unchanged)
        float* rowm = sc + w * SCP;
        float m = -1e30f;
        for (int i = lane; i < S_; i += 32) m = fmaxf(m, rowm[i]);
#pragma unroll
        for (int off = 16; off; off >>= 1)
            m = fmaxf(m, __shfl_xor_sync(FULL, m, off));
        float l = 0.f;
        for (int i = lane; i < S_; i += 32) {
            float s = rowm[i];
            float p = (s >= thr) ? __expf(s - m) : 0.f;
            rowm[i] = p;
            l += p;
        }
#pragma unroll
        for (int off = 16; off; off >>= 1)
            l += __shfl_xor_sync(FULL, l, off);
        if (lane == 0) s_rcp[w] = 1.0f / l;
    }
    __syncthreads();

    // ---- phase E: PV, 64-key chunks, double-buffered ----
    auto conv_p = [&](int ch) {
        __nv_bfloat16* pb = pt + (ch & 1) * PBUF;
#pragma unroll
        for (int it = 0; it < 2; it++) {
            int i = tid + it * 512;
            int r = i >> 6, k = i & 63;
            float p = sc[r * SCP + ch * CH64 + k];
            __nv_bfloat16 b0 = __float2bfloat16(p);
            pb[r * KTP + k] = b0;
            pb[16 * KTP + r * KTP + k] = __float2bfloat16(p - __bfloat162float(b0));
        }
    };

    conv_p(0);

    int kq = w >> 2;
    wmma::fragment<wmma::accumulator, 16, 16, 16, float> facc;
    wmma::fill_fragment(facc, 0.0f);

    for (int ch = 0; ch < NCH64; ch++) {
        if (ch + 1 < NCH64) asm volatile("cp.async.wait_group 1;");
        else                asm volatile("cp.async.wait_group 0;");
        __syncthreads();

        __nv_bfloat16* vbuf = kb + (ch & 1) * VBUF;
        __nv_bfloat16* pb   = pt + (ch & 1) * PBUF;
        {
            wmma::fragment<wmma::matrix_a, 16, 16, 16, __nv_bfloat16, wmma::row_major> pa0, pa1;
            wmma::fragment<wmma::matrix_b, 16, 16, 16, __nv_bfloat16, wmma::row_major> vb0, vb1;
            wmma::load_matrix_sync(pa0, pb + kq * 16, KTP);
            wmma::load_matrix_sync(pa1, pb + 16 * KTP + kq * 16, KTP);
            wmma::load_matrix_sync(vb0, vbuf + 0 * CH64 * KTP + (kq * 16) * KTP + nt * 16, KTP);
            wmma::load_matrix_sync(vb1, vbuf + 1 * CH64 * KTP + (kq * 16) * KTP + nt * 16, KTP);
            wmma::mma_sync(facc, pa0, vb0, facc);
            wmma::mma_sync(facc, pa0, vb1, facc);
            wmma::mma_sync(facc, pa1, vb0, facc);
        }
        if (ch + 1 < NCH64) conv_p(ch + 1);
        __syncthreads();
        if (ch + 2 < NCH64) load_v(ch + 2);
    }

    // ---- reduce 4 key-tiles, split, write A planes ----
    wmma::store_matrix_sync(stg + w * 256, facc, 16, wmma::mem_row_major);
    __syncthreads();
    for (int i = tid; i < 16 * HD_; i += 512) {
        int r = i >> 6, d = i & 63;
        int nt2 = d >> 4, c = d & 15;
        float v = stg[(0 * 4 + nt2) * 256 + r * 16 + c]
                + stg[(1 * 4 + nt2) * 256 + r * 16 + c]
                + stg[(2 * 4 + nt2) * 256 + r * 16 + c]
                + stg[(3 * 4 + nt2) * 256 + r * 16 + c];
        v *= s_rcp[r];
        size_t oi = ((size_t)b * S_ + q0 + r) * D_ + h * HD_ + d;
        __nv_bfloat16 b0 = __float2bfloat16(v);
        A0[oi] = b0;
        A1[oi] = __float2bfloat16(v - __bfloat162float(b0));
    }
}

// ---------------- launcher ----------------
extern "C" void kernel_launch(void* const* d_in, const int* in_sizes, int n_in,
                              void* d_out, int out_size)
{
    const float* X  = (const float*)d_in[0];
    const float* Wq = (const float*)d_in[1];
    const float* bq = (const float*)d_in[2];
    const float* Wk = (const float*)d_in[3];
    const float* bk = (const float*)d_in[4];
    const float* Wv = (const float*)d_in[5];
    const float* bv = (const float*)d_in[6];
    const float* Wo = (const float*)d_in[7];
    const float* bo = (const float*)d_in[8];

    static float *Qd = nullptr;
    static __nv_bfloat16 *X3[3], *K3[3], *V2[2], *A3[2], *W3[3];
    static bool init_done = false;
    if (!init_done) {
        cudaGetSymbolAddress((void**)&Qd, g_Q);
        __nv_bfloat16* base;
        cudaGetSymbolAddress((void**)&base, g_X3);
        for (int p = 0; p < 3; p++) X3[p] = base + (size_t)p * MROWS * D_;
        cudaGetSymbolAddress((void**)&base, g_K3);
        for (int p = 0; p < 3; p++) K3[p] = base + (size_t)p * MROWS * D_;
        cudaGetSymbolAddress((void**)&base, g_V2);
        for (int p = 0; p < 2; p++) V2[p] = base + (size_t)p * MROWS * D_;
        cudaGetSymbolAddress((void**)&base, g_A3);
        for (int p = 0; p < 2; p++) A3[p] = base + (size_t)p * MROWS * D_;
        cudaGetSymbolAddress((void**)&base, g_W3);
        for (int p = 0; p < 3; p++) W3[p] = base + (size_t)p * D_ * D_;
        cudaFuncSetAttribute(attn_tc,
                             cudaFuncAttributeMaxDynamicSharedMemorySize, AT_SMEM);
        cudaFuncSetAttribute(gemm_pipe<3>,
                             cudaFuncAttributeMaxDynamicSharedMemorySize, GEMM_SMEM_3);
        cudaFuncSetAttribute(gemm_pipe<2>,
                             cudaFuncAttributeMaxDynamicSharedMemorySize, GEMM_SMEM_2);
        init_done = true;
    }

    const int NX4 = MROWS * D_ / 4;
    const int NW4 = D_ * D_ / 4;
    dim3 ggrid(D_ / 128, MROWS / 128);

    split3_kernel<<<NX4 / 256, 256>>>(X, X3[0], X3[1], X3[2], NX4);

    split3_kernel<<<NW4 / 256, 256>>>(Wq, W3[0], W3[1], W3[2], NW4);
    gemm_pipe<3><<<ggrid, 256, GEMM_SMEM_3>>>(X3[0], X3[1], X3[2],
        W3[0], W3[1], W3[2], bq, Qd, nullptr, nullptr, nullptr, 1);
    split3_kernel<<<NW4 / 256, 256>>>(Wk, W3[0], W3[1], W3[2], NW4);
    gemm_pipe<3><<<ggrid, 256, GEMM_SMEM_3>>>(X3[0], X3[1], X3[2],
        W3[0], W3[1], W3[2], bk, nullptr, K3[0], K3[1], K3[2], 2);
    split3_kernel<<<NW4 / 256, 256>>>(Wv, W3[0], W3[1], nullptr, NW4);
    gemm_pipe<2><<<ggrid, 256, GEMM_SMEM_2>>>(X3[0], X3[1], nullptr,
        W3[0], W3[1], nullptr, bv, nullptr, V2[0], V2[1], nullptr, 3);

    attn_tc<<<dim3(S_ / 16, H_, B_), 512, AT_SMEM>>>(
        Qd, K3[0], K3[1], K3[2], V2[0], V2[1], A3[0], A3[1]);

    split3_kernel<<<NW4 / 256, 256>>>(Wo, W3[0], W3[1], nullptr, NW4);
    gemm_pipe<2><<<ggrid, 256, GEMM_SMEM_2>>>(A3[0], A3[1], nullptr,
        W3[0], W3[1], nullptr, bo, (float*)d_out, nullptr, nullptr, nullptr, 0);
}

// round 15
// speedup vs baseline: 1.0582x; 1.0582x over previous
#include <cuda_runtime.h>
#include <cuda_bf16.h>
#include <mma.h>
#include <math.h>

using namespace nvcuda;

#define B_  2
#define S_  2048
#define D_  1024
#define H_  16
#define HD_ 64
#define KSEL 409
#define RANK0 (S_ - KSEL)   /* 1639 */
#define MROWS (B_ * S_)     /* 4096 */

// ---------------- device scratch ----------------
__device__ __align__(256) float g_Q[MROWS * D_];                 // [b,h,s,hd] fp32
__device__ __align__(256) __nv_bfloat16 g_K3[3][MROWS * D_];     // K planes [b,h,s,hd]
__device__ __align__(256) __nv_bfloat16 g_V2[2][MROWS * D_];     // V planes
__device__ __align__(256) __nv_bfloat16 g_X3[3][MROWS * D_];     // X planes
__device__ __align__(256) __nv_bfloat16 g_A3[2][MROWS * D_];     // attn-out planes [b,s,d]
__device__ __align__(256) __nv_bfloat16 g_W3[3][D_ * D_];        // weight planes

// ---------------- split3 ----------------
__global__ __launch_bounds__(256) void split3_kernel(
    const float* __restrict__ src,
    __nv_bfloat16* __restrict__ d0, __nv_bfloat16* __restrict__ d1,
    __nv_bfloat16* __restrict__ d2, int n4)
{
    int i = blockIdx.x * 256 + threadIdx.x;
    if (i >= n4) return;
    float4 v = ((const float4*)src)[i];
    float va[4] = { v.x, v.y, v.z, v.w };
    unsigned short u0[4], u1[4], u2[4];
#pragma unroll
    for (int e = 0; e < 4; e++) {
        float r = va[e];
        __nv_bfloat16 b0 = __float2bfloat16(r);  r -= __bfloat162float(b0);
        __nv_bfloat16 b1 = __float2bfloat16(r);  r -= __bfloat162float(b1);
        __nv_bfloat16 b2 = __float2bfloat16(r);
        u0[e] = __bfloat16_as_ushort(b0);
        u1[e] = __bfloat16_as_ushort(b1);
        u2[e] = __bfloat16_as_ushort(b2);
    }
    uint2 w;
    w.x = (unsigned)u0[0] | ((unsigned)u0[1] << 16);
    w.y = (unsigned)u0[2] | ((unsigned)u0[3] << 16);
    ((uint2*)d0)[i] = w;
    w.x = (unsigned)u1[0] | ((unsigned)u1[1] << 16);
    w.y = (unsigned)u1[2] | ((unsigned)u1[3] << 16);
    ((uint2*)d1)[i] = w;
    if (d2) {
        w.x = (unsigned)u2[0] | ((unsigned)u2[1] << 16);
        w.y = (unsigned)u2[2] | ((unsigned)u2[3] << 16);
        ((uint2*)d2)[i] = w;
    }
}

// ======== pipelined split-bf16 GEMM with fused split epilogue ========
#define GBKP 40
#define GSTG 36
#define PLANE_SZ (128 * GBKP)
#define GEMM_SMEM_3 (2 * 3 * 2 * PLANE_SZ * 2)
#define GEMM_SMEM_2 (2 * 2 * 2 * PLANE_SZ * 2)

template<int PLANES>
__global__ __launch_bounds__(256, 1) void gemm_pipe(
    const __nv_bfloat16* __restrict__ A0, const __nv_bfloat16* __restrict__ A1,
    const __nv_bfloat16* __restrict__ A2,
    const __nv_bfloat16* __restrict__ B0, const __nv_bfloat16* __restrict__ B1,
    const __nv_bfloat16* __restrict__ B2,
    const float* __restrict__ bias, float* __restrict__ C,
    __nv_bfloat16* __restrict__ P0, __nv_bfloat16* __restrict__ P1,
    __nv_bfloat16* __restrict__ P2, int mode)
{
    extern __shared__ char smraw[];
    __nv_bfloat16* sbase = (__nv_bfloat16*)smraw;
    const int STAGE_SZ = PLANES * 2 * PLANE_SZ;
    const __nv_bfloat16* Ap[3] = { A0, A1, A2 };
    const __nv_bfloat16* Bp[3] = { B0, B1, B2 };

    const int K = D_;
    int tid = threadIdx.x;
    int wid = tid >> 5;
    int wm = wid >> 2;
    int wn = wid & 3;
    int bm = blockIdx.y * 128;
    int bn = blockIdx.x * 128;

    wmma::fragment<wmma::accumulator, 16, 16, 16, float> fc[4][2];
#pragma unroll
    for (int i = 0; i < 4; i++)
#pragma unroll
        for (int j = 0; j < 2; j++) wmma::fill_fragment(fc[i][j], 0.0f);

    int row0 = tid >> 2, col0 = (tid & 3) * 8;
    int row1 = (tid + 256) >> 2, col1 = ((tid + 256) & 3) * 8;

    auto load_stage = [&](int t, int buf) {
        int k0 = t * 32;
#pragma unroll
        for (int p = 0; p < PLANES; p++) {
            __nv_bfloat16* sA = sbase + buf * STAGE_SZ + p * PLANE_SZ;
            __nv_bfloat16* sB = sbase + buf * STAGE_SZ + (PLANES + p) * PLANE_SZ;
            {
                const __nv_bfloat16* ga = Ap[p] + (size_t)(bm + row0) * K + k0 + col0;
                const __nv_bfloat16* gb = Bp[p] + (size_t)(bn + row0) * K + k0 + col0;
                unsigned da = (unsigned)__cvta_generic_to_shared(sA + row0 * GBKP + col0);
                unsigned db = (unsigned)__cvta_generic_to_shared(sB + row0 * GBKP + col0);
                asm volatile("cp.async.cg.shared.global [%0], [%1], 16;" :: "r"(da), "l"(ga));
                asm volatile("cp.async.cg.shared.global [%0], [%1], 16;" :: "r"(db), "l"(gb));
            }
            {
                const __nv_bfloat16* ga = Ap[p] + (size_t)(bm + row1) * K + k0 + col1;
                const __nv_bfloat16* gb = Bp[p] + (size_t)(bn + row1) * K + k0 + col1;
                unsigned da = (unsigned)__cvta_generic_to_shared(sA + row1 * GBKP + col1);
                unsigned db = (unsigned)__cvta_generic_to_shared(sB + row1 * GBKP + col1);
                asm volatile("cp.async.cg.shared.global [%0], [%1], 16;" :: "r"(da), "l"(ga));
                asm volatile("cp.async.cg.shared.global [%0], [%1], 16;" :: "r"(db), "l"(gb));
            }
        }
        asm volatile("cp.async.commit_group;");
    };

    load_stage(0, 0);
    load_stage(1, 1);

    const int NT = K / 32;
    for (int t = 0; t < NT; t++) {
        if (t + 1 < NT) asm volatile("cp.async.wait_group 1;");
        else            asm volatile("cp.async.wait_group 0;");
        __syncthreads();

        int buf = t & 1;
        __nv_bfloat16* stA = sbase + buf * STAGE_SZ;
        __nv_bfloat16* stB = stA + PLANES * PLANE_SZ;
#pragma unroll
        for (int ks = 0; ks < 2; ks++) {
            wmma::fragment<wmma::matrix_b, 16, 16, 16, __nv_bfloat16, wmma::col_major> fb[PLANES][2];
#pragma unroll
            for (int p = 0; p < PLANES; p++)
#pragma unroll
                for (int j = 0; j < 2; j++)
                    wmma::load_matrix_sync(fb[p][j],
                        stB + p * PLANE_SZ + (wn * 32 + j * 16) * GBKP + ks * 16, GBKP);
#pragma unroll
            for (int sa = 0; sa < PLANES; sa++) {
                wmma::fragment<wmma::matrix_a, 16, 16, 16, __nv_bfloat16, wmma::row_major> fa[4];
#pragma unroll
                for (int i = 0; i < 4; i++)
                    wmma::load_matrix_sync(fa[i],
                        stA + sa * PLANE_SZ + (wm * 64 + i * 16) * GBKP + ks * 16, GBKP);
#pragma unroll
                for (int sb = 0; sb < PLANES - sa; sb++)
#pragma unroll
                    for (int i = 0; i < 4; i++)
#pragma unroll
                        for (int j = 0; j < 2; j++)
                            wmma::mma_sync(fc[i][j], fa[i], fb[sb][j], fc[i][j]);
            }
        }
        __syncthreads();
        if (t + 2 < NT) load_stage(t + 2, buf);
    }

    float* stage = (float*)smraw + wid * 64 * GSTG;
#pragma unroll
    for (int i = 0; i < 4; i++)
#pragma unroll
        for (int j = 0; j < 2; j++)
            wmma::store_matrix_sync(stage + (i * 16) * GSTG + j * 16, fc[i][j],
                                    GSTG, wmma::mem_row_major);
    __syncwarp();

    int lane = tid & 31;
    for (int idx = lane; idx < 64 * 32; idx += 32) {
        int r = idx >> 5, c = idx & 31;
        int gr = bm + wm * 64 + r;
        int gc = bn + wn * 32 + c;
        float v = stage[r * GSTG + c] + bias[gc];
        if (mode == 0) {
            C[(size_t)gr * D_ + gc] = v;
        } else {
            int b = gr >> 11;
            int s = gr & (S_ - 1);
            int h = gc >> 6;
            int hd = gc & (HD_ - 1);
            size_t oi = (((size_t)(b * H_ + h)) * S_ + s) * HD_ + hd;
            if (mode == 1) {
                C[oi] = v;
            } else {
                __nv_bfloat16 b0 = __float2bfloat16(v);
                float r1 = v - __bfloat162float(b0);
                __nv_bfloat16 b1 = __float2bfloat16(r1);
                P0[oi] = b0;
                P1[oi] = b1;
                if (mode == 2) P2[oi] = __float2bfloat16(r1 - __bfloat162float(b1));
            }
        }
    }
}

// ======== tensor-core fused sparse attention (race-free single-barrier, depth-1) ========
#define SCP    2056
#define CH64   64
#define NCH64  (S_ / CH64)          /* 32 */
#define KTP    72

#define KBUF   (3 * CH64 * KTP)
#define VBUF   (2 * CH64 * KTP)
#define PBUF   (2 * 16 * KTP)
#define STGBUF 3072                 /* floats per staging buffer */

#define AT_SC   0                                /* 131584 */
#define AT_KV   131584                           /* 55296 */
#define AT_Q    (AT_KV + 55296)                  /* 6912 */
#define AT_P    (AT_Q + 6912)                    /* 9216 */
#define AT_STG  (AT_P + 9216)                    /* 24576 (hist alias) */
#define AT_RCP  (AT_STG + 24576)                 /* 64 */
#define AT_SMEM (AT_RCP + 64)                    /* 227648 */

__global__ __launch_bounds__(512, 1) void attn_tc(
    const float* __restrict__ Q,
    const __nv_bfloat16* __restrict__ K0, const __nv_bfloat16* __restrict__ K1,
    const __nv_bfloat16* __restrict__ K2,
    const __nv_bfloat16* __restrict__ V0, const __nv_bfloat16* __restrict__ V1,
    __nv_bfloat16* __restrict__ A0, __nv_bfloat16* __restrict__ A1)
{
    extern __shared__ char smem[];
    float* sc = (float*)(smem + AT_SC);
    __nv_bfloat16* kb = (__nv_bfloat16*)(smem + AT_KV);
    __nv_bfloat16* qt = (__nv_bfloat16*)(smem + AT_Q);
    __nv_bfloat16* pt = (__nv_bfloat16*)(smem + AT_P);
    float* stg   = (float*)(smem + AT_STG);
    int*   hist  = (int*)(smem + AT_STG);
    float* s_rcp = (float*)(smem + AT_RCP);

    int tid  = threadIdx.x;
    int lane = tid & 31;
    int w    = tid >> 5;
    int b    = blockIdx.z, h = blockIdx.y;
    int q0   = blockIdx.x * 16;
    size_t hb = ((size_t)(b * H_ + h)) * S_ * HD_;
    const __nv_bfloat16* Kp[3] = { K0 + hb, K1 + hb, K2 + hb };
    const __nv_bfloat16* Vp[2] = { V0 + hb, V1 + hb };

    auto load_k = [&](int ch) {
#pragma unroll
        for (int it = 0; it < 3; it++) {
            int i = tid + it * 512;
            int plane = i >> 9;
            int rem = i & 511;
            int row = rem >> 3, seg = rem & 7;
            const __nv_bfloat16* g = Kp[plane] + (size_t)(ch * CH64 + row) * HD_ + seg * 8;
            unsigned d = (unsigned)__cvta_generic_to_shared(
                kb + (ch & 1) * KBUF + plane * CH64 * KTP + row * KTP + seg * 8);
            asm volatile("cp.async.cg.shared.global [%0], [%1], 16;" :: "r"(d), "l"(g));
        }
        asm volatile("cp.async.commit_group;");
    };
    auto load_v = [&](int ch) {
#pragma unroll
        for (int it = 0; it < 2; it++) {
            int i = tid + it * 512;
            int plane = i >> 9;
            int rem = i & 511;
            int row = rem >> 3, seg = rem & 7;
            const __nv_bfloat16* g = Vp[plane] + (size_t)(ch * CH64 + row) * HD_ + seg * 8;
            unsigned d = (unsigned)__cvta_generic_to_shared(
                kb + (ch & 1) * VBUF + plane * CH64 * KTP + row * KTP + seg * 8);
            asm volatile("cp.async.cg.shared.global [%0], [%1], 16;" :: "r"(d), "l"(g));
        }
        asm volatile("cp.async.commit_group;");
    };

    // prime K chunk 0 (depth-1; overlaps Q split)
    load_k(0);

    // ---- phase A: Q load, scale 1/8 (exact), 3-split ----
    for (int i = tid; i < 16 * HD_; i += 512) {
        int r = i >> 6, d = i & 63;
        float v = Q[hb + (size_t)(q0 + r) * HD_ + d] * 0.125f;
        __nv_bfloat16 b0 = __float2bfloat16(v);  v -= __bfloat162float(b0);
        __nv_bfloat16 b1 = __float2bfloat16(v);  v -= __bfloat162float(b1);
        __nv_bfloat16 b2 = __float2bfloat16(v);
        qt[0 * 16 * KTP + r * KTP + d] = b0;
        qt[1 * 16 * KTP + r * KTP + d] = b1;
        qt[2 * 16 * KTP + r * KTP + d] = b2;
    }
    __syncthreads();

    int nt = w & 3, kh = w >> 2;
    wmma::fragment<wmma::matrix_a, 16, 16, 16, __nv_bfloat16, wmma::row_major> fqa[3];
#pragma unroll
    for (int p = 0; p < 3; p++)
        wmma::load_matrix_sync(fqa[p], qt + p * 16 * KTP + kh * 16, KTP);

    // ---- phase B: QK^T — wait, BARRIER, then issue next load (race-free) ----
    const int SA[6] = {0, 0, 1, 1, 0, 2};
    const int SB[6] = {0, 1, 0, 1, 2, 0};
    wmma::fragment<wmma::accumulator, 16, 16, 16, float> pacc;  // kh==0 carry
    for (int ch = 0; ch < NCH64; ch++) {
        asm volatile("cp.async.wait_group 0;");   // my copies for buf ch&1 done
        __syncthreads();                           // visible to all; iter ch-1 readers drained
        if (ch + 1 < NCH64) load_k(ch + 1);        // targets buf (ch+1)&1 (readers drained)

        __nv_bfloat16* kbuf = kb + (ch & 1) * KBUF;
        wmma::fragment<wmma::accumulator, 16, 16, 16, float> acc;
        wmma::fill_fragment(acc, 0.0f);
        {
            wmma::fragment<wmma::matrix_b, 16, 16, 16, __nv_bfloat16, wmma::col_major> fkb[3];
#pragma unroll
            for (int p = 0; p < 3; p++)
                wmma::load_matrix_sync(fkb[p],
                    kbuf + p * CH64 * KTP + (nt * 16) * KTP + kh * 16, KTP);
#pragma unroll
            for (int pr = 0; pr < 6; pr++)
                wmma::mma_sync(acc, fqa[SA[pr]], fkb[SB[pr]], acc);
        }
        if (kh > 0) {
            wmma::store_matrix_sync(stg + (ch & 1) * STGBUF + (nt * 3 + kh - 1) * 256,
                                    acc, 16, wmma::mem_row_major);
        } else {
            if (ch > 0) {   // reduce chunk ch-1 partials (visible via top barrier)
                wmma::fragment<wmma::accumulator, 16, 16, 16, float> o;
#pragma unroll
                for (int s = 0; s < 3; s++) {
                    wmma::load_matrix_sync(o,
                        stg + ((ch - 1) & 1) * STGBUF + (nt * 3 + s) * 256, 16,
                        wmma::mem_row_major);
#pragma unroll
                    for (int e = 0; e < pacc.num_elements; e++) pacc.x[e] += o.x[e];
                }
                wmma::store_matrix_sync(sc + (ch - 1) * CH64 + nt * 16, pacc, SCP,
                                        wmma::mem_row_major);
            }
            pacc = acc;
        }
    }
    __syncthreads();
    if (kh == 0) {   // reduce final chunk
        wmma::fragment<wmma::accumulator, 16, 16, 16, float> o;
#pragma unroll
        for (int s = 0; s < 3; s++) {
            wmma::load_matrix_sync(o,
                stg + ((NCH64 - 1) & 1) * STGBUF + (nt * 3 + s) * 256, 16,
                wmma::mem_row_major);
#pragma unroll
            for (int e = 0; e < pacc.num_elements; e++) pacc.x[e] += o.x[e];
        }
        wmma::store_matrix_sync(sc + (NCH64 - 1) * CH64 + nt * 16, pacc, SCP,
                                wmma::mem_row_major);
    }
    __syncthreads();

    // prime V chunk 0 — hidden behind phase C (kb is free, all K groups retired)
    load_v(0);

    // ---- phase C: warp-private atomic radix select (R11) + softmax ----
    {
        unsigned pref = 0u; int rank = RANK0;
        const float* rowp = sc + w * SCP;
        int* hw = hist + w * 256;
        for (int pass = 0; pass < 4; pass++) {
            int shift = 24 - pass * 8;
#pragma unroll
            for (int j = lane; j < 256; j += 32) hw[j] = 0;
            __syncwarp();
            for (int i = lane; i < S_; i += 32) {
                unsigned bits = __float_as_uint(rowp[i]);
                unsigned u = (bits & 0x80000000u) ? ~bits : (bits | 0x80000000u);
                bool ok = (pass == 0) ||
                          ((u >> (shift + 8)) == (pref >> (shift + 8)));
                if (ok) atomicAdd(&hw[(u >> shift) & 255], 1);
            }
            __syncwarp();
            int c8[8]; int cnt = 0;
#pragma unroll
            for (int j = 0; j < 8; j++) { c8[j] = hw[lane * 8 + j]; cnt += c8[j]; }
            int inc = cnt;
#pragma unroll
            for (int off = 1; off < 32; off <<= 1) {
                int n = __shfl_up_sync(0xffffffffu, inc, off);
                if (lane >= off) inc += n;
            }
            int excl = inc - cnt;
            bool found = (rank >= excl) && (rank < inc);
            unsigned npref = pref; int nrank = rank;
            if (found) {
                int rr = rank - excl; int sel = -1;
#pragma unroll
                for (int j = 0; j < 8; j++) {
                    if (sel < 0) { if (rr < c8[j]) sel = j; else rr -= c8[j]; }
                }
                npref = pref | ((unsigned)(lane * 8 + sel) << shift);
                nrank = rr;
            }
            unsigned mask = __ballot_sync(0xffffffffu, found);
            int src = __ffs(mask) - 1;
            pref = __shfl_sync(0xffffffffu, npref, src);
            rank = __shfl_sync(0xffffffffu, nrank, src);
            __syncwarp();
        }
        unsigned tb = (pref & 0x80000000u) ? (pref ^ 0x80000000u) : ~pref;
        float thr = __uint_as_float(tb);

        float* rowm = sc + w * SCP;
        float m = -1e30f;
        for (int i = lane; i < S_; i += 32) m = fmaxf(m, rowm[i]);
#pragma unroll
        for (int off = 16; off; off >>= 1)
            m = fmaxf(m, __shfl_xor_sync(0xffffffffu, m, off));
        float l = 0.f;
        for (int i = lane; i < S_; i += 32) {
            float s = rowm[i];
            float p = (s >= thr) ? __expf(s - m) : 0.f;
            rowm[i] = p;
            l += p;
        }
#pragma unroll
        for (int off = 16; off; off >>= 1)
            l += __shfl_xor_sync(0xffffffffu, l, off);
        if (lane == 0) s_rcp[w] = 1.0f / l;
    }
    __syncthreads();   // sc(probs) visible to all; hist dead

    // ---- phase E: PV — same race-free single-barrier pattern ----
    auto conv_p = [&](int ch) {
        __nv_bfloat16* pb = pt + (ch & 1) * PBUF;
#pragma unroll
        for (int it = 0; it < 2; it++) {
            int i = tid + it * 512;
            int r = i >> 6, k = i & 63;
            float p = sc[r * SCP + ch * CH64 + k];
            __nv_bfloat16 b0 = __float2bfloat16(p);
            pb[r * KTP + k] = b0;
            pb[16 * KTP + r * KTP + k] = __float2bfloat16(p - __bfloat162float(b0));
        }
    };

    conv_p(0);   // pt[0]; visible to readers via iter-0 top barrier

    int kq = w >> 2;
    wmma::fragment<wmma::accumulator, 16, 16, 16, float> facc;
    wmma::fill_fragment(facc, 0.0f);

    for (int ch = 0; ch < NCH64; ch++) {
        asm volatile("cp.async.wait_group 0;");
        __syncthreads();
        if (ch + 1 < NCH64) load_v(ch + 1);

        __nv_bfloat16* vbuf = kb + (ch & 1) * VBUF;
        __nv_bfloat16* pb   = pt + (ch & 1) * PBUF;
        {
            wmma::fragment<wmma::matrix_a, 16, 16, 16, __nv_bfloat16, wmma::row_major> pa0, pa1;
            wmma::fragment<wmma::matrix_b, 16, 16, 16, __nv_bfloat16, wmma::row_major> vb0, vb1;
            wmma::load_matrix_sync(pa0, pb + kq * 16, KTP);
            wmma::load_matrix_sync(pa1, pb + 16 * KTP + kq * 16, KTP);
            wmma::load_matrix_sync(vb0, vbuf + 0 * CH64 * KTP + (kq * 16) * KTP + nt * 16, KTP);
            wmma::load_matrix_sync(vb1, vbuf + 1 * CH64 * KTP + (kq * 16) * KTP + nt * 16, KTP);
            wmma::mma_sync(facc, pa0, vb0, facc);
            wmma::mma_sync(facc, pa0, vb1, facc);
            wmma::mma_sync(facc, pa1, vb0, facc);
        }
        if (ch + 1 < NCH64) conv_p(ch + 1);   // pt[(ch+1)&1]: readers drained at top barrier
    }

    // ---- reduce 4 key-tiles, split, write A planes ----
    __syncthreads();   // stg (phase-B staging) fully dead; reuse for output
    wmma::store_matrix_sync(stg + w * 256, facc, 16, wmma::mem_row_major);
    __syncthreads();
    for (int i = tid; i < 16 * HD_; i += 512) {
        int r = i >> 6, d = i & 63;
        int nt2 = d >> 4, c = d & 15;
        float v = stg[(0 * 4 + nt2) * 256 + r * 16 + c]
                + stg[(1 * 4 + nt2) * 256 + r * 16 + c]
                + stg[(2 * 4 + nt2) * 256 + r * 16 + c]
                + stg[(3 * 4 + nt2) * 256 + r * 16 + c];
        v *= s_rcp[r];
        size_t oi = ((size_t)b * S_ + q0 + r) * D_ + h * HD_ + d;
        __nv_bfloat16 b0 = __float2bfloat16(v);
        A0[oi] = b0;
        A1[oi] = __float2bfloat16(v - __bfloat162float(b0));
    }
}

// ---------------- launcher ----------------
extern "C" void kernel_launch(void* const* d_in, const int* in_sizes, int n_in,
                              void* d_out, int out_size)
{
    const float* X  = (const float*)d_in[0];
    const float* Wq = (const float*)d_in[1];
    const float* bq = (const float*)d_in[2];
    const float* Wk = (const float*)d_in[3];
    const float* bk = (const float*)d_in[4];
    const float* Wv = (const float*)d_in[5];
    const float* bv = (const float*)d_in[6];
    const float* Wo = (const float*)d_in[7];
    const float* bo = (const float*)d_in[8];

    static float *Qd = nullptr;
    static __nv_bfloat16 *X3[3], *K3[3], *V2[2], *A3[2], *W3[3];
    static bool init_done = false;
    if (!init_done) {
        cudaGetSymbolAddress((void**)&Qd, g_Q);
        __nv_bfloat16* base;
        cudaGetSymbolAddress((void**)&base, g_X3);
        for (int p = 0; p < 3; p++) X3[p] = base + (size_t)p * MROWS * D_;
        cudaGetSymbolAddress((void**)&base, g_K3);
        for (int p = 0; p < 3; p++) K3[p] = base + (size_t)p * MROWS * D_;
        cudaGetSymbolAddress((void**)&base, g_V2);
        for (int p = 0; p < 2; p++) V2[p] = base + (size_t)p * MROWS * D_;
        cudaGetSymbolAddress((void**)&base, g_A3);
        for (int p = 0; p < 2; p++) A3[p] = base + (size_t)p * MROWS * D_;
        cudaGetSymbolAddress((void**)&base, g_W3);
        for (int p = 0; p < 3; p++) W3[p] = base + (size_t)p * D_ * D_;
        cudaFuncSetAttribute(attn_tc,
                             cudaFuncAttributeMaxDynamicSharedMemorySize, AT_SMEM);
        cudaFuncSetAttribute(gemm_pipe<3>,
                             cudaFuncAttributeMaxDynamicSharedMemorySize, GEMM_SMEM_3);
        cudaFuncSetAttribute(gemm_pipe<2>,
                             cudaFuncAttributeMaxDynamicSharedMemorySize, GEMM_SMEM_2);
        init_done = true;
    }

    const int NX4 = MROWS * D_ / 4;
    const int NW4 = D_ * D_ / 4;
    dim3 ggrid(D_ / 128, MROWS / 128);

    split3_kernel<<<NX4 / 256, 256>>>(X, X3[0], X3[1], X3[2], NX4);

    split3_kernel<<<NW4 / 256, 256>>>(Wq, W3[0], W3[1], W3[2], NW4);
    gemm_pipe<3><<<ggrid, 256, GEMM_SMEM_3>>>(X3[0], X3[1], X3[2],
        W3[0], W3[1], W3[2], bq, Qd, nullptr, nullptr, nullptr, 1);
    split3_kernel<<<NW4 / 256, 256>>>(Wk, W3[0], W3[1], W3[2], NW4);
    gemm_pipe<3><<<ggrid, 256, GEMM_SMEM_3>>>(X3[0], X3[1], X3[2],
        W3[0], W3[1], W3[2], bk, nullptr, K3[0], K3[1], K3[2], 2);
    split3_kernel<<<NW4 / 256, 256>>>(Wv, W3[0], W3[1], nullptr, NW4);
    gemm_pipe<2><<<ggrid, 256, GEMM_SMEM_2>>>(X3[0], X3[1], nullptr,
        W3[0], W3[1], nullptr, bv, nullptr, V2[0], V2[1], nullptr, 3);

    attn_tc<<<dim3(S_ / 16, H_, B_), 512, AT_SMEM>>>(
        Qd, K3[0], K3[1], K3[2], V2[0], V2[1], A3[0], A3[1]);

    split3_kernel<<<NW4 / 256, 256>>>(Wo, W3[0], W3[1], nullptr, NW4);
    gemm_pipe<2><<<ggrid, 256, GEMM_SMEM_2>>>(A3[0], A3[1], nullptr,
        W3[0], W3[1], nullptr, bo, (float*)d_out, nullptr, nullptr, nullptr, 0);
}